// round 1
// baseline (speedup 1.0000x reference)
#include <cuda_runtime.h>

#define N_NODES_C  50000
#define N_EDGES_C  800000
#define N_GRAPHS_C 2000
#define EMB   300
#define EMB4  75          // EMB / 4
#define HID   600         // 2*EMB
#define FEAT  512
#define OUTD  256
#define NLAYER 5

// ---------------- scratch (device globals; no cudaMalloc allowed) ------------
__device__ float4 g_h[N_NODES_C * EMB4];       // [N, 300] as float4
__device__ float4 g_aggr[N_NODES_C * EMB4];    // [N, 300]
__device__ float  g_tmp[N_NODES_C * HID];      // [N, 600]
__device__ float  g_pool[N_GRAPHS_C * EMB];    // per-graph sums
__device__ int    g_cnt[N_GRAPHS_C];           // per-graph node counts
__device__ float  g_hg[N_GRAPHS_C * EMB];      // per-graph mean
__device__ float  g_p[N_GRAPHS_C * (FEAT/2)];
__device__ float  g_pb[N_GRAPHS_C * (FEAT/2)];

// ---------------- kernels ----------------------------------------------------

// h[i] = x_emb1[x[i,0]] + x_emb2[x[i,1]]
__global__ void k_init_h(const int* __restrict__ x,
                         const float4* __restrict__ emb1,
                         const float4* __restrict__ emb2)
{
    int gid = blockIdx.x * blockDim.x + threadIdx.x;
    if (gid >= N_NODES_C * EMB4) return;
    int node = gid / EMB4;
    int q    = gid - node * EMB4;
    int x0 = x[node * 2 + 0];
    int x1 = x[node * 2 + 1];
    float4 a = emb1[x0 * EMB4 + q];
    float4 b = emb2[x1 * EMB4 + q];
    float4 r; r.x = a.x + b.x; r.y = a.y + b.y; r.z = a.z + b.z; r.w = a.w + b.w;
    g_h[gid] = r;
}

// aggr[i] = h[i] + edge_e1[l][4] + edge_e2[l][0]   (self-loop contribution)
__global__ void k_aggr_init(const float4* __restrict__ e1_self,
                            const float4* __restrict__ e2_self)
{
    int gid = blockIdx.x * blockDim.x + threadIdx.x;
    if (gid >= N_NODES_C * EMB4) return;
    int q = gid % EMB4;
    float4 h = g_h[gid];
    float4 a = e1_self[q];
    float4 b = e2_self[q];
    float4 r; r.x = h.x + a.x + b.x; r.y = h.y + a.y + b.y;
    r.z = h.z + a.z + b.z; r.w = h.w + a.w + b.w;
    g_aggr[gid] = r;
}

// scatter:  aggr[dst] += h[src] + e1[ea0] + e2[ea1]   for each real edge
__global__ void k_edge_scatter(const int* __restrict__ edge_index,
                               const int* __restrict__ edge_attr,
                               const float4* __restrict__ e1,   // edge_e1 + l*5*EMB
                               const float4* __restrict__ e2)   // edge_e2 + l*3*EMB
{
    int gid = blockIdx.x * blockDim.x + threadIdx.x;
    if (gid >= N_EDGES_C * EMB4) return;
    int e = gid / EMB4;
    int q = gid - e * EMB4;
    int src = edge_index[e];
    int dst = edge_index[N_EDGES_C + e];
    int a0  = edge_attr[2 * e + 0];
    int a1  = edge_attr[2 * e + 1];
    float4 h  = g_h[src * EMB4 + q];
    float4 v1 = e1[a0 * EMB4 + q];
    float4 v2 = e2[a1 * EMB4 + q];
    float4 m; m.x = h.x + v1.x + v2.x; m.y = h.y + v1.y + v2.y;
    m.z = h.z + v1.z + v2.z; m.w = h.w + v1.w + v2.w;
    float* out = (float*)&g_aggr[dst * EMB4 + q];
    atomicAdd(out + 0, m.x);
    atomicAdd(out + 1, m.y);
    atomicAdd(out + 2, m.z);
    atomicAdd(out + 3, m.w);
}

// C[M,N] = act(A[M,K] @ B[K,N] + bias[N]) ; act = relu if doRelu
#define BM 64
#define BN 64
#define BK 16
#define ASTRIDE 68   // BM + 4 pad, keeps float4 alignment, kills bank conflicts

__global__ void k_gemm_bias(const float* __restrict__ A,
                            const float* __restrict__ B,
                            const float* __restrict__ bias,
                            float* __restrict__ C,
                            int M, int N, int K, int doRelu)
{
    __shared__ float As[BK * ASTRIDE];
    __shared__ float Bs[BK * BN];

    int tid = threadIdx.x;               // 256 threads
    int tx = tid & 15;                   // 0..15 -> col group
    int ty = tid >> 4;                   // 0..15 -> row group
    int rowBase = blockIdx.y * BM;
    int colBase = blockIdx.x * BN;

    float acc[4][4];
    #pragma unroll
    for (int i = 0; i < 4; i++)
        #pragma unroll
        for (int j = 0; j < 4; j++) acc[i][j] = 0.f;

    for (int k0 = 0; k0 < K; k0 += BK) {
        // load A tile (BM x BK) transposed into As[k][r]
        #pragma unroll
        for (int i = tid; i < BM * BK; i += 256) {
            int r = i >> 4;              // i / BK
            int k = i & 15;              // i % BK
            int gr = rowBase + r, gk = k0 + k;
            As[k * ASTRIDE + r] = (gr < M && gk < K) ? A[gr * K + gk] : 0.f;
        }
        // load B tile (BK x BN)
        #pragma unroll
        for (int i = tid; i < BK * BN; i += 256) {
            int k = i >> 6;              // i / BN
            int c = i & 63;              // i % BN
            int gk = k0 + k, gc = colBase + c;
            Bs[k * BN + c] = (gk < K && gc < N) ? B[gk * N + gc] : 0.f;
        }
        __syncthreads();
        #pragma unroll
        for (int k = 0; k < BK; k++) {
            float4 a4 = *(const float4*)&As[k * ASTRIDE + ty * 4];
            float4 b4 = *(const float4*)&Bs[k * BN + tx * 4];
            float a[4] = {a4.x, a4.y, a4.z, a4.w};
            float b[4] = {b4.x, b4.y, b4.z, b4.w};
            #pragma unroll
            for (int i = 0; i < 4; i++)
                #pragma unroll
                for (int j = 0; j < 4; j++)
                    acc[i][j] += a[i] * b[j];
        }
        __syncthreads();
    }

    #pragma unroll
    for (int i = 0; i < 4; i++) {
        int gr = rowBase + ty * 4 + i;
        if (gr >= M) continue;
        #pragma unroll
        for (int j = 0; j < 4; j++) {
            int gc = colBase + tx * 4 + j;
            if (gc >= N) continue;
            float v = acc[i][j] + bias[gc];
            if (doRelu) v = fmaxf(v, 0.f);
            C[gr * N + gc] = v;
        }
    }
}

__global__ void k_zero_pool()
{
    int gid = blockIdx.x * blockDim.x + threadIdx.x;
    if (gid < N_GRAPHS_C * EMB) g_pool[gid] = 0.f;
    if (gid < N_GRAPHS_C) g_cnt[gid] = 0;
}

__global__ void k_pool_sum(const int* __restrict__ batch)
{
    int gid = blockIdx.x * blockDim.x + threadIdx.x;
    if (gid >= N_NODES_C * EMB4) return;
    int node = gid / EMB4;
    int q    = gid - node * EMB4;
    int g = batch[node];
    float4 v = g_h[gid];
    float* dst = &g_pool[g * EMB + q * 4];
    atomicAdd(dst + 0, v.x);
    atomicAdd(dst + 1, v.y);
    atomicAdd(dst + 2, v.z);
    atomicAdd(dst + 3, v.w);
}

__global__ void k_pool_cnt(const int* __restrict__ batch)
{
    int gid = blockIdx.x * blockDim.x + threadIdx.x;
    if (gid >= N_NODES_C) return;
    atomicAdd(&g_cnt[batch[gid]], 1);
}

__global__ void k_pool_mean()
{
    int gid = blockIdx.x * blockDim.x + threadIdx.x;
    if (gid >= N_GRAPHS_C * EMB) return;
    int g = gid / EMB;
    int c = g_cnt[g];
    float denom = (c > 0) ? (float)c : 1.f;
    g_hg[gid] = g_pool[gid] / denom;
}

// ---------------- launch -----------------------------------------------------
extern "C" void kernel_launch(void* const* d_in, const int* in_sizes, int n_in,
                              void* d_out, int out_size)
{
    const int*   x          = (const int*)  d_in[0];
    const int*   edge_index = (const int*)  d_in[1];
    const int*   edge_attr  = (const int*)  d_in[2];
    const int*   batch      = (const int*)  d_in[3];
    const float* x_emb1     = (const float*)d_in[4];
    const float* x_emb2     = (const float*)d_in[5];
    const float* edge_e1    = (const float*)d_in[6];   // [L,5,EMB]
    const float* edge_e2    = (const float*)d_in[7];   // [L,3,EMB]
    const float* W1         = (const float*)d_in[8];   // [L,EMB,2EMB]
    const float* b1         = (const float*)d_in[9];   // [L,2EMB]
    const float* W2         = (const float*)d_in[10];  // [L,2EMB,EMB]
    const float* b2         = (const float*)d_in[11];  // [L,EMB]
    const float* feat_W     = (const float*)d_in[12];  // [EMB,FEAT]
    const float* feat_b     = (const float*)d_in[13];
    const float* p0_W       = (const float*)d_in[14];
    const float* p0_b       = (const float*)d_in[15];
    const float* p1_W       = (const float*)d_in[16];
    const float* p1_b       = (const float*)d_in[17];
    const float* p2_W       = (const float*)d_in[18];
    const float* p2_b       = (const float*)d_in[19];

    float* out_hg   = (float*)d_out;                       // [G, FEAT]
    float* out_proj = (float*)d_out + N_GRAPHS_C * FEAT;   // [G, OUT]

    const int T = 256;
    const int nodeElems = N_NODES_C * EMB4;
    const int edgeElems = N_EDGES_C * EMB4;

    // scratch pointers (device-symbol addresses are valid in device code only,
    // so GEMM kernels take raw pointers obtained via the symbols below)
    // We can take addresses of __device__ globals on the host side with
    // cudaGetSymbolAddress only outside capture -> instead just pass them as
    // template-free raw pointers using the fact that device globals have fixed
    // addresses: use small wrapper kernels? Simpler: cudaGetSymbolAddress is
    // capture-safe (host-side query, no graph node). Do it once per call.
    static float* p_h = nullptr, *p_aggr = nullptr, *p_tmp = nullptr,
                *p_hg = nullptr, *p_p = nullptr, *p_pb = nullptr;
    if (!p_h) {
        void* tmp;
        cudaGetSymbolAddress(&tmp, g_h);    p_h    = (float*)tmp;
        cudaGetSymbolAddress(&tmp, g_aggr); p_aggr = (float*)tmp;
        cudaGetSymbolAddress(&tmp, g_tmp);  p_tmp  = (float*)tmp;
        cudaGetSymbolAddress(&tmp, g_hg);   p_hg   = (float*)tmp;
        cudaGetSymbolAddress(&tmp, g_p);    p_p    = (float*)tmp;
        cudaGetSymbolAddress(&tmp, g_pb);   p_pb   = (float*)tmp;
    }

    // 1. initial node embedding
    k_init_h<<<(nodeElems + T - 1) / T, T>>>(x, (const float4*)x_emb1,
                                             (const float4*)x_emb2);

    // 2. GINE layers
    for (int l = 0; l < NLAYER; l++) {
        const float* e1l = edge_e1 + l * 5 * EMB;
        const float* e2l = edge_e2 + l * 3 * EMB;

        k_aggr_init<<<(nodeElems + T - 1) / T, T>>>(
            (const float4*)(e1l + 4 * EMB), (const float4*)(e2l + 0 * EMB));

        k_edge_scatter<<<(edgeElems + T - 1) / T, T>>>(
            edge_index, edge_attr, (const float4*)e1l, (const float4*)e2l);

        // tmp = relu(aggr @ W1[l] + b1[l])   [N,300]x[300,600]
        {
            dim3 grid((HID + BN - 1) / BN, (N_NODES_C + BM - 1) / BM);
            k_gemm_bias<<<grid, 256>>>(p_aggr, W1 + l * EMB * HID,
                                       b1 + l * HID, p_tmp,
                                       N_NODES_C, HID, EMB, 1);
        }
        // h = tmp @ W2[l] + b2[l] (+relu if l < L-1)   [N,600]x[600,300]
        {
            dim3 grid((EMB + BN - 1) / BN, (N_NODES_C + BM - 1) / BM);
            k_gemm_bias<<<grid, 256>>>(p_tmp, W2 + l * HID * EMB,
                                       b2 + l * EMB, p_h,
                                       N_NODES_C, EMB, HID, (l < NLAYER - 1) ? 1 : 0);
        }
    }

    // 3. global mean pool
    k_zero_pool<<<(N_GRAPHS_C * EMB + T - 1) / T, T>>>();
    k_pool_sum<<<(nodeElems + T - 1) / T, T>>>(batch);
    k_pool_cnt<<<(N_NODES_C + T - 1) / T, T>>>(batch);
    k_pool_mean<<<(N_GRAPHS_C * EMB + T - 1) / T, T>>>();

    // 4. feat_lin: hg = mean @ feat_W + feat_b  -> output 0
    {
        dim3 grid((FEAT + BN - 1) / BN, (N_GRAPHS_C + BM - 1) / BM);
        k_gemm_bias<<<grid, 256>>>(p_hg, feat_W, feat_b, out_hg,
                                   N_GRAPHS_C, FEAT, EMB, 0);
    }
    // 5. pred head
    {
        dim3 grid((FEAT/2 + BN - 1) / BN, (N_GRAPHS_C + BM - 1) / BM);
        k_gemm_bias<<<grid, 256>>>(out_hg, p0_W, p0_b, p_p,
                                   N_GRAPHS_C, FEAT/2, FEAT, 1);
        k_gemm_bias<<<grid, 256>>>(p_p, p1_W, p1_b, p_pb,
                                   N_GRAPHS_C, FEAT/2, FEAT/2, 1);
    }
    {
        dim3 grid((OUTD + BN - 1) / BN, (N_GRAPHS_C + BM - 1) / BM);
        k_gemm_bias<<<grid, 256>>>(p_pb, p2_W, p2_b, out_proj,
                                   N_GRAPHS_C, OUTD, FEAT/2, 0);
    }
}

// round 2
// speedup vs baseline: 2.1046x; 2.1046x over previous
#include <cuda_runtime.h>

#define N_NODES_C  50000
#define N_EDGES_C  800000
#define N_GRAPHS_C 2000
#define EMB   300
#define EMB4  75          // EMB / 4
#define HID   600         // 2*EMB
#define FEAT  512
#define OUTD  256
#define NLAYER 5

// ---------------- scratch (device globals; no cudaMalloc allowed) ------------
__device__ float4 g_h[N_NODES_C * EMB4];       // [N, 300] as float4
__device__ float4 g_aggr[N_NODES_C * EMB4];    // [N, 300]
__device__ float  g_tmp[N_NODES_C * HID];      // [N, 600]
__device__ float  g_pool[N_GRAPHS_C * EMB];    // per-graph sums
__device__ int    g_cnt[N_GRAPHS_C];           // per-graph node counts
__device__ float  g_hg[N_GRAPHS_C * EMB];      // per-graph mean
__device__ float  g_p[N_GRAPHS_C * (FEAT/2)];
__device__ float  g_pb[N_GRAPHS_C * (FEAT/2)];
// CSR
__device__ int    g_deg[N_NODES_C];
__device__ int    g_rowptr[N_NODES_C];
__device__ int    g_cursor[N_NODES_C];
__device__ int    g_csr[N_EDGES_C];            // src | (combo<<16)
__device__ float4 g_ee[15 * EMB4];             // per-layer combo table

// ---------------- helpers ----------------------------------------------------
__device__ __forceinline__ void fma2(unsigned long long& d,
                                     unsigned long long a,
                                     unsigned long long b)
{
    asm("fma.rn.f32x2 %0, %1, %2, %0;" : "+l"(d) : "l"(a), "l"(b));
}
__device__ __forceinline__ unsigned long long bcast2(float a)
{
    unsigned long long r;
    unsigned u = __float_as_uint(a);
    asm("mov.b64 %0, {%1, %1};" : "=l"(r) : "r"(u));
    return r;
}
__device__ __forceinline__ void unpack2(unsigned long long v, float& lo, float& hi)
{
    unsigned a, b;
    asm("mov.b64 {%0, %1}, %2;" : "=r"(a), "=r"(b) : "l"(v));
    lo = __uint_as_float(a);
    hi = __uint_as_float(b);
}

// ---------------- kernels ----------------------------------------------------

// h[i] = x_emb1[x[i,0]] + x_emb2[x[i,1]]
__global__ void k_init_h(const int* __restrict__ x,
                         const float4* __restrict__ emb1,
                         const float4* __restrict__ emb2)
{
    int gid = blockIdx.x * blockDim.x + threadIdx.x;
    if (gid >= N_NODES_C * EMB4) return;
    int node = gid / EMB4;
    int q    = gid - node * EMB4;
    int x0 = x[node * 2 + 0];
    int x1 = x[node * 2 + 1];
    float4 a = emb1[x0 * EMB4 + q];
    float4 b = emb2[x1 * EMB4 + q];
    float4 r; r.x = a.x + b.x; r.y = a.y + b.y; r.z = a.z + b.z; r.w = a.w + b.w;
    g_h[gid] = r;
}

// ------- CSR build ------
__global__ void k_zero_deg()
{
    int gid = blockIdx.x * blockDim.x + threadIdx.x;
    if (gid < N_NODES_C) g_deg[gid] = 0;
}

__global__ void k_hist(const int* __restrict__ edge_index)
{
    int e = blockIdx.x * blockDim.x + threadIdx.x;
    if (e >= N_EDGES_C) return;
    atomicAdd(&g_deg[edge_index[N_EDGES_C + e]], 1);
}

__global__ void k_scan()   // 1 block, 1024 threads
{
    __shared__ int s[1024];
    int t = threadIdx.x;
    const int CH = (N_NODES_C + 1023) / 1024;   // 49
    int base = t * CH;
    int loc = 0;
    for (int i = 0; i < CH; i++) {
        int idx = base + i;
        if (idx < N_NODES_C) loc += g_deg[idx];
    }
    s[t] = loc;
    __syncthreads();
    for (int off = 1; off < 1024; off <<= 1) {
        int v = (t >= off) ? s[t - off] : 0;
        __syncthreads();
        s[t] += v;
        __syncthreads();
    }
    int run = s[t] - loc;   // exclusive prefix
    for (int i = 0; i < CH; i++) {
        int idx = base + i;
        if (idx < N_NODES_C) {
            g_rowptr[idx] = run;
            g_cursor[idx] = run;
            run += g_deg[idx];
        }
    }
}

__global__ void k_fill(const int* __restrict__ edge_index,
                       const int* __restrict__ edge_attr)
{
    int e = blockIdx.x * blockDim.x + threadIdx.x;
    if (e >= N_EDGES_C) return;
    int dst = edge_index[N_EDGES_C + e];
    int src = edge_index[e];
    int a0 = edge_attr[2 * e + 0];
    int a1 = edge_attr[2 * e + 1];
    int pos = atomicAdd(&g_cursor[dst], 1);
    g_csr[pos] = src | ((a0 * 3 + a1) << 16);
}

// per-layer: ee[c] = e1[c/3] + e2[c%3],  c in [0,15)
__global__ void k_combo(const float4* __restrict__ e1,
                        const float4* __restrict__ e2)
{
    int gid = blockIdx.x * blockDim.x + threadIdx.x;
    if (gid >= 15 * EMB4) return;
    int c = gid / EMB4;
    int q = gid - c * EMB4;
    float4 a = e1[(c / 3) * EMB4 + q];
    float4 b = e2[(c % 3) * EMB4 + q];
    float4 r; r.x = a.x + b.x; r.y = a.y + b.y; r.z = a.z + b.z; r.w = a.w + b.w;
    g_ee[gid] = r;
}

// aggr[node] = h[node] + ee[selfloop] + sum_{e in row} (h[src_e] + ee[combo_e])
__global__ void k_gather()   // grid = N_NODES, block = 96 (75 active)
{
    int node = blockIdx.x;
    int q = threadIdx.x;
    if (q >= EMB4) return;
    float4 acc = g_h[node * EMB4 + q];
    float4 sl = g_ee[12 * EMB4 + q];   // combo (4,0) -> 4*3+0 = 12
    acc.x += sl.x; acc.y += sl.y; acc.z += sl.z; acc.w += sl.w;
    int s = g_rowptr[node];
    int e = s + g_deg[node];
    for (int p = s; p < e; p++) {
        int pk = g_csr[p];
        int src = pk & 0xffff;
        int cb  = pk >> 16;
        float4 hv = g_h[src * EMB4 + q];
        float4 ev = g_ee[cb * EMB4 + q];
        acc.x += hv.x + ev.x; acc.y += hv.y + ev.y;
        acc.z += hv.z + ev.z; acc.w += hv.w + ev.w;
    }
    g_aggr[node * EMB4 + q] = acc;
}

// ------- GEMM: C[M,N] = act(A[M,K] @ B[K,N] + bias), 128x128x8, f32x2 FMA ----
#define GBM 128
#define GBN 128
#define GBK 8
#define APAD 132

__global__ void __launch_bounds__(256, 2)
k_gemm128(const float* __restrict__ A, const float* __restrict__ B,
          const float* __restrict__ bias, float* __restrict__ C,
          int M, int N, int K, int doRelu)
{
    __shared__ float As[2][GBK][APAD];
    __shared__ float Bs[2][GBK][GBN];

    int tid = threadIdx.x;
    int tx = tid & 15;          // 0..15 col group
    int ty = tid >> 4;          // 0..15 row group
    int rowBase = blockIdx.y * GBM;
    int colBase = blockIdx.x * GBN;

    int aRow = tid >> 1;        // 0..127
    int aK   = (tid & 1) * 4;   // 0 or 4
    int bK   = tid >> 5;        // 0..7
    int bC   = (tid & 31) * 4;  // 0..124

    unsigned long long acc[8][4];
    #pragma unroll
    for (int i = 0; i < 8; i++)
        #pragma unroll
        for (int j = 0; j < 4; j++) acc[i][j] = 0ull;

    int nk = (K + GBK - 1) / GBK;

    // preload tile 0 to regs
    float4 aReg = make_float4(0.f, 0.f, 0.f, 0.f);
    float4 bReg = make_float4(0.f, 0.f, 0.f, 0.f);
    {
        int gr = rowBase + aRow;
        if (gr < M && aK < K) aReg = *(const float4*)&A[(long)gr * K + aK];
        int gc = colBase + bC;
        if (gc < N && bK < K) bReg = *(const float4*)&B[(long)bK * N + gc];
    }
    // store tile 0
    As[0][aK + 0][aRow] = aReg.x;
    As[0][aK + 1][aRow] = aReg.y;
    As[0][aK + 2][aRow] = aReg.z;
    As[0][aK + 3][aRow] = aReg.w;
    *(float4*)&Bs[0][bK][bC] = bReg;
    __syncthreads();

    int buf = 0;
    for (int t = 0; t < nk; t++) {
        // prefetch tile t+1 (guards zero-fill past end)
        int k0n = (t + 1) * GBK;
        aReg = make_float4(0.f, 0.f, 0.f, 0.f);
        bReg = make_float4(0.f, 0.f, 0.f, 0.f);
        {
            int gr = rowBase + aRow, gk = k0n + aK;
            if (gr < M && gk < K) aReg = *(const float4*)&A[(long)gr * K + gk];
            int gc = colBase + bC, gkb = k0n + bK;
            if (gc < N && gkb < K) bReg = *(const float4*)&B[(long)gkb * N + gc];
        }
        // compute on buf
        #pragma unroll
        for (int k = 0; k < GBK; k++) {
            const float* asr = &As[buf][k][ty * 8];
            float4 a0 = *(const float4*)asr;
            float4 a1 = *(const float4*)(asr + 4);
            ulonglong2 bA = *(const ulonglong2*)&Bs[buf][k][tx * 8];
            ulonglong2 bB = *(const ulonglong2*)&Bs[buf][k][tx * 8 + 4];
            unsigned long long bv[4] = { bA.x, bA.y, bB.x, bB.y };
            float av[8] = { a0.x, a0.y, a0.z, a0.w, a1.x, a1.y, a1.z, a1.w };
            #pragma unroll
            for (int i = 0; i < 8; i++) {
                unsigned long long ap = bcast2(av[i]);
                #pragma unroll
                for (int j = 0; j < 4; j++) fma2(acc[i][j], ap, bv[j]);
            }
        }
        // store prefetched into other buffer
        int nb = buf ^ 1;
        As[nb][aK + 0][aRow] = aReg.x;
        As[nb][aK + 1][aRow] = aReg.y;
        As[nb][aK + 2][aRow] = aReg.z;
        As[nb][aK + 3][aRow] = aReg.w;
        *(float4*)&Bs[nb][bK][bC] = bReg;
        __syncthreads();
        buf = nb;
    }

    // epilogue
    int gc0 = colBase + tx * 8;
    float bs8[8];
    #pragma unroll
    for (int j = 0; j < 8; j++) {
        int gc = gc0 + j;
        bs8[j] = (gc < N) ? bias[gc] : 0.f;
    }
    #pragma unroll
    for (int i = 0; i < 8; i++) {
        int gr = rowBase + ty * 8 + i;
        if (gr >= M) continue;
        float v[8];
        #pragma unroll
        for (int jp = 0; jp < 4; jp++) unpack2(acc[i][jp], v[2 * jp], v[2 * jp + 1]);
        #pragma unroll
        for (int j = 0; j < 8; j++) {
            v[j] += bs8[j];
            if (doRelu) v[j] = fmaxf(v[j], 0.f);
        }
        if (gc0 + 7 < N) {
            *(float4*)&C[(long)gr * N + gc0]     = make_float4(v[0], v[1], v[2], v[3]);
            *(float4*)&C[(long)gr * N + gc0 + 4] = make_float4(v[4], v[5], v[6], v[7]);
        } else {
            #pragma unroll
            for (int j = 0; j < 8; j++)
                if (gc0 + j < N) C[(long)gr * N + gc0 + j] = v[j];
        }
    }
}

// ------- pooling -------
__global__ void k_zero_pool()
{
    int gid = blockIdx.x * blockDim.x + threadIdx.x;
    if (gid < N_GRAPHS_C * EMB) g_pool[gid] = 0.f;
    if (gid < N_GRAPHS_C) g_cnt[gid] = 0;
}

__global__ void k_pool_sum(const int* __restrict__ batch)
{
    int gid = blockIdx.x * blockDim.x + threadIdx.x;
    if (gid >= N_NODES_C * EMB4) return;
    int node = gid / EMB4;
    int q    = gid - node * EMB4;
    int g = batch[node];
    float4 v = g_h[gid];
    float* dst = &g_pool[g * EMB + q * 4];
    atomicAdd(dst + 0, v.x);
    atomicAdd(dst + 1, v.y);
    atomicAdd(dst + 2, v.z);
    atomicAdd(dst + 3, v.w);
}

__global__ void k_pool_cnt(const int* __restrict__ batch)
{
    int gid = blockIdx.x * blockDim.x + threadIdx.x;
    if (gid >= N_NODES_C) return;
    atomicAdd(&g_cnt[batch[gid]], 1);
}

__global__ void k_pool_mean()
{
    int gid = blockIdx.x * blockDim.x + threadIdx.x;
    if (gid >= N_GRAPHS_C * EMB) return;
    int g = gid / EMB;
    int c = g_cnt[g];
    float denom = (c > 0) ? (float)c : 1.f;
    g_hg[gid] = g_pool[gid] / denom;
}

// ---------------- launch -----------------------------------------------------
extern "C" void kernel_launch(void* const* d_in, const int* in_sizes, int n_in,
                              void* d_out, int out_size)
{
    const int*   x          = (const int*)  d_in[0];
    const int*   edge_index = (const int*)  d_in[1];
    const int*   edge_attr  = (const int*)  d_in[2];
    const int*   batch      = (const int*)  d_in[3];
    const float* x_emb1     = (const float*)d_in[4];
    const float* x_emb2     = (const float*)d_in[5];
    const float* edge_e1    = (const float*)d_in[6];   // [L,5,EMB]
    const float* edge_e2    = (const float*)d_in[7];   // [L,3,EMB]
    const float* W1         = (const float*)d_in[8];   // [L,EMB,2EMB]
    const float* b1         = (const float*)d_in[9];   // [L,2EMB]
    const float* W2         = (const float*)d_in[10];  // [L,2EMB,EMB]
    const float* b2         = (const float*)d_in[11];  // [L,EMB]
    const float* feat_W     = (const float*)d_in[12];  // [EMB,FEAT]
    const float* feat_b     = (const float*)d_in[13];
    const float* p0_W       = (const float*)d_in[14];
    const float* p0_b       = (const float*)d_in[15];
    const float* p1_W       = (const float*)d_in[16];
    const float* p1_b       = (const float*)d_in[17];
    const float* p2_W       = (const float*)d_in[18];
    const float* p2_b       = (const float*)d_in[19];

    float* out_hg   = (float*)d_out;                       // [G, FEAT]
    float* out_proj = (float*)d_out + N_GRAPHS_C * FEAT;   // [G, OUT]

    const int T = 256;
    const int nodeElems = N_NODES_C * EMB4;

    static float *p_h = nullptr, *p_aggr = nullptr, *p_tmp = nullptr,
                 *p_hg = nullptr, *p_p = nullptr, *p_pb = nullptr;
    if (!p_h) {
        void* tmp;
        cudaGetSymbolAddress(&tmp, g_h);    p_h    = (float*)tmp;
        cudaGetSymbolAddress(&tmp, g_aggr); p_aggr = (float*)tmp;
        cudaGetSymbolAddress(&tmp, g_tmp);  p_tmp  = (float*)tmp;
        cudaGetSymbolAddress(&tmp, g_hg);   p_hg   = (float*)tmp;
        cudaGetSymbolAddress(&tmp, g_p);    p_p    = (float*)tmp;
        cudaGetSymbolAddress(&tmp, g_pb);   p_pb   = (float*)tmp;
    }

    // 1. initial node embedding
    k_init_h<<<(nodeElems + T - 1) / T, T>>>(x, (const float4*)x_emb1,
                                             (const float4*)x_emb2);

    // 2. CSR build (once; reused by all layers)
    k_zero_deg<<<(N_NODES_C + T - 1) / T, T>>>();
    k_hist<<<(N_EDGES_C + T - 1) / T, T>>>(edge_index);
    k_scan<<<1, 1024>>>();
    k_fill<<<(N_EDGES_C + T - 1) / T, T>>>(edge_index, edge_attr);

    // 3. GINE layers
    for (int l = 0; l < NLAYER; l++) {
        const float* e1l = edge_e1 + l * 5 * EMB;
        const float* e2l = edge_e2 + l * 3 * EMB;

        k_combo<<<(15 * EMB4 + T - 1) / T, T>>>((const float4*)e1l,
                                                (const float4*)e2l);
        k_gather<<<N_NODES_C, 96>>>();

        // tmp = relu(aggr @ W1[l] + b1[l])  [N,300]x[300,600]
        {
            dim3 grid((HID + GBN - 1) / GBN, (N_NODES_C + GBM - 1) / GBM);
            k_gemm128<<<grid, 256>>>(p_aggr, W1 + l * EMB * HID,
                                     b1 + l * HID, p_tmp,
                                     N_NODES_C, HID, EMB, 1);
        }
        // h = tmp @ W2[l] + b2[l] (+relu if l<L-1)  [N,600]x[600,300]
        {
            dim3 grid((EMB + GBN - 1) / GBN, (N_NODES_C + GBM - 1) / GBM);
            k_gemm128<<<grid, 256>>>(p_tmp, W2 + l * HID * EMB,
                                     b2 + l * EMB, p_h,
                                     N_NODES_C, EMB, HID, (l < NLAYER - 1) ? 1 : 0);
        }
    }

    // 4. global mean pool
    k_zero_pool<<<(N_GRAPHS_C * EMB + T - 1) / T, T>>>();
    k_pool_sum<<<(nodeElems + T - 1) / T, T>>>(batch);
    k_pool_cnt<<<(N_NODES_C + T - 1) / T, T>>>(batch);
    k_pool_mean<<<(N_GRAPHS_C * EMB + T - 1) / T, T>>>();

    // 5. feat_lin -> output hg
    {
        dim3 grid((FEAT + GBN - 1) / GBN, (N_GRAPHS_C + GBM - 1) / GBM);
        k_gemm128<<<grid, 256>>>(p_hg, feat_W, feat_b, out_hg,
                                 N_GRAPHS_C, FEAT, EMB, 0);
    }
    // 6. pred head
    {
        dim3 grid((FEAT / 2 + GBN - 1) / GBN, (N_GRAPHS_C + GBM - 1) / GBM);
        k_gemm128<<<grid, 256>>>(out_hg, p0_W, p0_b, p_p,
                                 N_GRAPHS_C, FEAT / 2, FEAT, 1);
        k_gemm128<<<grid, 256>>>(p_p, p1_W, p1_b, p_pb,
                                 N_GRAPHS_C, FEAT / 2, FEAT / 2, 1);
    }
    {
        dim3 grid((OUTD + GBN - 1) / GBN, (N_GRAPHS_C + GBM - 1) / GBM);
        k_gemm128<<<grid, 256>>>(p_pb, p2_W, p2_b, out_proj,
                                 N_GRAPHS_C, OUTD, FEAT / 2, 0);
    }
}

// round 4
// speedup vs baseline: 3.1871x; 1.5143x over previous
#include <cuda_runtime.h>
#include <cuda_bf16.h>
#include <cstdint>

#define N_NODES_C  50000
#define N_EDGES_C  800000
#define N_GRAPHS_C 2000
#define EMB   300
#define EMB4  75
#define HID   600
#define FEAT  512
#define OUTD  256
#define NLAYER 5

#define MROWS_PAD 50048          // 391 * 128
#define K1PAD 320                // EMB padded to mult of 32
#define K2PAD 640                // HID padded to mult of 32
#define W1T_ROWS 640             // HID padded to 5*128
#define W2T_ROWS 384             // EMB padded to 3*128

// ---------------- scratch ----------------------------------------------------
__device__ float4 g_h[N_NODES_C * EMB4];                       // [N,300] fp32
__device__ __nv_bfloat16 g_aggr_hi[MROWS_PAD * K1PAD];
__device__ __nv_bfloat16 g_aggr_lo[MROWS_PAD * K1PAD];
__device__ __nv_bfloat16 g_tmp_hi[(size_t)MROWS_PAD * K2PAD];
__device__ __nv_bfloat16 g_tmp_lo[(size_t)MROWS_PAD * K2PAD];
__device__ __nv_bfloat16 g_w1t_hi[W1T_ROWS * K1PAD];
__device__ __nv_bfloat16 g_w1t_lo[W1T_ROWS * K1PAD];
__device__ __nv_bfloat16 g_w2t_hi[W2T_ROWS * K2PAD];
__device__ __nv_bfloat16 g_w2t_lo[W2T_ROWS * K2PAD];
__device__ float  g_pool[N_GRAPHS_C * EMB];
__device__ int    g_cnt[N_GRAPHS_C];
__device__ float  g_hg[N_GRAPHS_C * EMB];
__device__ float  g_p[N_GRAPHS_C * (FEAT/2)];
__device__ float  g_pb[N_GRAPHS_C * (FEAT/2)];
__device__ int    g_deg[N_NODES_C];
__device__ int    g_rowptr[N_NODES_C];
__device__ int    g_cursor[N_NODES_C];
__device__ int    g_csr[N_EDGES_C];            // src | (combo<<16)
__device__ float4 g_ee[15 * EMB4];

// ---------------- PTX helpers -------------------------------------------------
__device__ __forceinline__ uint32_t smem_u32(const void* p) {
    uint32_t a;
    asm("{ .reg .u64 t; cvta.to.shared.u64 t, %1; cvt.u32.u64 %0, t; }" : "=r"(a) : "l"(p));
    return a;
}
__device__ __forceinline__ void cp16(uint32_t saddr, const void* g) {
    asm volatile("cp.async.cg.shared.global [%0], [%1], 16;" :: "r"(saddr), "l"(g));
}
#define CP_COMMIT() asm volatile("cp.async.commit_group;" ::: "memory")
#define CP_WAIT1()  asm volatile("cp.async.wait_group 1;" ::: "memory")
#define CP_WAIT0()  asm volatile("cp.async.wait_group 0;" ::: "memory")

__device__ __forceinline__ void ldsm4(uint32_t* f, uint32_t addr) {
    asm volatile("ldmatrix.sync.aligned.m8n8.x4.shared.b16 {%0,%1,%2,%3}, [%4];"
        : "=r"(f[0]), "=r"(f[1]), "=r"(f[2]), "=r"(f[3]) : "r"(addr));
}
__device__ __forceinline__ void mma_bf16(float* c, const uint32_t* a,
                                         uint32_t b0, uint32_t b1) {
    asm volatile("mma.sync.aligned.m16n8k16.row.col.f32.bf16.bf16.f32 "
        "{%0,%1,%2,%3}, {%4,%5,%6,%7}, {%8,%9}, {%0,%1,%2,%3};"
        : "+f"(c[0]), "+f"(c[1]), "+f"(c[2]), "+f"(c[3])
        : "r"(a[0]), "r"(a[1]), "r"(a[2]), "r"(a[3]), "r"(b0), "r"(b1));
}
__device__ __forceinline__ uint32_t pack_bf2(__nv_bfloat16 a, __nv_bfloat16 b) {
    __nv_bfloat162 t; t.x = a; t.y = b;
    return *(uint32_t*)&t;
}

__device__ __forceinline__ void fma2(unsigned long long& d, unsigned long long a,
                                     unsigned long long b) {
    asm("fma.rn.f32x2 %0, %1, %2, %0;" : "+l"(d) : "l"(a), "l"(b));
}
__device__ __forceinline__ unsigned long long bcast2(float a) {
    unsigned long long r; unsigned u = __float_as_uint(a);
    asm("mov.b64 %0, {%1, %1};" : "=l"(r) : "r"(u));
    return r;
}
__device__ __forceinline__ void unpack2(unsigned long long v, float& lo, float& hi) {
    unsigned a, b;
    asm("mov.b64 {%0, %1}, %2;" : "=r"(a), "=r"(b) : "l"(v));
    lo = __uint_as_float(a); hi = __uint_as_float(b);
}

// ---------------- small kernels ----------------------------------------------
__global__ void k_init_h(const int* __restrict__ x,
                         const float4* __restrict__ emb1,
                         const float4* __restrict__ emb2)
{
    int gid = blockIdx.x * blockDim.x + threadIdx.x;
    if (gid >= N_NODES_C * EMB4) return;
    int node = gid / EMB4, q = gid - node * EMB4;
    float4 a = emb1[x[node * 2 + 0] * EMB4 + q];
    float4 b = emb2[x[node * 2 + 1] * EMB4 + q];
    float4 r; r.x = a.x + b.x; r.y = a.y + b.y; r.z = a.z + b.z; r.w = a.w + b.w;
    g_h[gid] = r;
}

__global__ void k_zero_deg()
{
    int gid = blockIdx.x * blockDim.x + threadIdx.x;
    if (gid < N_NODES_C) g_deg[gid] = 0;
}

__global__ void k_hist(const int* __restrict__ edge_index)
{
    int e = blockIdx.x * blockDim.x + threadIdx.x;
    if (e >= N_EDGES_C) return;
    atomicAdd(&g_deg[edge_index[N_EDGES_C + e]], 1);
}

__global__ void k_scan()
{
    __shared__ int s[1024];
    int t = threadIdx.x;
    const int CH = (N_NODES_C + 1023) / 1024;
    int base = t * CH;
    int loc = 0;
    for (int i = 0; i < CH; i++) {
        int idx = base + i;
        if (idx < N_NODES_C) loc += g_deg[idx];
    }
    s[t] = loc;
    __syncthreads();
    for (int off = 1; off < 1024; off <<= 1) {
        int v = (t >= off) ? s[t - off] : 0;
        __syncthreads();
        s[t] += v;
        __syncthreads();
    }
    int run = s[t] - loc;
    for (int i = 0; i < CH; i++) {
        int idx = base + i;
        if (idx < N_NODES_C) {
            g_rowptr[idx] = run; g_cursor[idx] = run;
            run += g_deg[idx];
        }
    }
}

__global__ void k_fill(const int* __restrict__ edge_index,
                       const int* __restrict__ edge_attr)
{
    int e = blockIdx.x * blockDim.x + threadIdx.x;
    if (e >= N_EDGES_C) return;
    int dst = edge_index[N_EDGES_C + e];
    int src = edge_index[e];
    int a0 = edge_attr[2 * e + 0], a1 = edge_attr[2 * e + 1];
    int pos = atomicAdd(&g_cursor[dst], 1);
    g_csr[pos] = src | ((a0 * 3 + a1) << 16);
}

__global__ void k_combo(const float4* __restrict__ e1, const float4* __restrict__ e2)
{
    int gid = blockIdx.x * blockDim.x + threadIdx.x;
    if (gid >= 15 * EMB4) return;
    int c = gid / EMB4, q = gid - c * EMB4;
    float4 a = e1[(c / 3) * EMB4 + q];
    float4 b = e2[(c % 3) * EMB4 + q];
    float4 r; r.x = a.x + b.x; r.y = a.y + b.y; r.z = a.z + b.z; r.w = a.w + b.w;
    g_ee[gid] = r;
}

// gather -> write aggr as split bf16, zero-padded to K1PAD
__global__ void k_gather()
{
    int node = blockIdx.x;
    int q = threadIdx.x;
    if (q >= 80) return;
    __nv_bfloat16* dst_hi = &g_aggr_hi[(size_t)node * K1PAD + q * 4];
    __nv_bfloat16* dst_lo = &g_aggr_lo[(size_t)node * K1PAD + q * 4];
    if (q >= EMB4) {   // pad cols 300..319
        *(uint2*)dst_hi = make_uint2(0, 0);
        *(uint2*)dst_lo = make_uint2(0, 0);
        return;
    }
    float4 acc = g_h[node * EMB4 + q];
    float4 sl = g_ee[12 * EMB4 + q];
    acc.x += sl.x; acc.y += sl.y; acc.z += sl.z; acc.w += sl.w;
    int s = g_rowptr[node];
    int e = s + g_deg[node];
    for (int p = s; p < e; p++) {
        int pk = g_csr[p];
        int src = pk & 0xffff, cb = pk >> 16;
        float4 hv = g_h[src * EMB4 + q];
        float4 ev = g_ee[cb * EMB4 + q];
        acc.x += hv.x + ev.x; acc.y += hv.y + ev.y;
        acc.z += hv.z + ev.z; acc.w += hv.w + ev.w;
    }
    float v[4] = { acc.x, acc.y, acc.z, acc.w };
    __nv_bfloat16 hi[4], lo[4];
    #pragma unroll
    for (int i = 0; i < 4; i++) {
        hi[i] = __float2bfloat16(v[i]);
        lo[i] = __float2bfloat16(v[i] - __bfloat162float(hi[i]));
    }
    *(uint2*)dst_hi = *(uint2*)hi;
    *(uint2*)dst_lo = *(uint2*)lo;
}

// W [K,N] fp32 -> WT split [Npad, Kpad] bf16 (transposed, zero-padded)
__global__ void k_convW(const float* __restrict__ W,
                        __nv_bfloat16* __restrict__ T_hi,
                        __nv_bfloat16* __restrict__ T_lo,
                        int K, int N, int Kpad, int Npad)
{
    int gid = blockIdx.x * blockDim.x + threadIdx.x;
    if (gid >= Npad * Kpad) return;
    int n = gid / Kpad, k = gid - n * Kpad;
    float v = (n < N && k < K) ? W[k * N + n] : 0.f;
    __nv_bfloat16 h = __float2bfloat16(v);
    T_hi[gid] = h;
    T_lo[gid] = __float2bfloat16(v - __bfloat162float(h));
}

// ---------------- split-bf16 mma.sync GEMM -----------------------------------
// C[M,N] = act(A @ B^T + bias); A [Mpad,Kpad], B [Npad,Kpad], both split hi/lo.
// Block 128x128, 8 warps (4 row x 2 col), warp tile 32x64, BK=32, double buffer.
#define ROWP 40                       // smem row stride in bf16 elems (80B)
#define ARR_B (128 * ROWP * 2)        // 10240 bytes per array
#define BUF_B (4 * ARR_B)             // 40960 bytes per buffer
#define MMA_SMEM (2 * BUF_B)          // 81920

__global__ void __launch_bounds__(256)
k_mma_gemm(const __nv_bfloat16* __restrict__ A_hi, const __nv_bfloat16* __restrict__ A_lo,
           const __nv_bfloat16* __restrict__ B_hi, const __nv_bfloat16* __restrict__ B_lo,
           const float* __restrict__ bias,
           int M, int Nreal, int Kpad,
           float* __restrict__ outF, int outFStride,
           __nv_bfloat16* __restrict__ outH_hi, __nv_bfloat16* __restrict__ outH_lo,
           int outHStride, int outMode /*0=split bf16+relu, 1=fp32*/, int doRelu)
{
    extern __shared__ char smem[];
    const int tid = threadIdx.x;
    const int lane = tid & 31, wid = tid >> 5;
    const int warp_m = wid & 3, warp_n = wid >> 2;
    const int rowBase = blockIdx.y * 128, colBase = blockIdx.x * 128;
    uint32_t sb = smem_u32(smem);

    const __nv_bfloat16* gb[4] = {
        A_hi + (size_t)rowBase * Kpad, A_lo + (size_t)rowBase * Kpad,
        B_hi + (size_t)colBase * Kpad, B_lo + (size_t)colBase * Kpad };

    float acc[2][8][4];
    #pragma unroll
    for (int i = 0; i < 2; i++)
        #pragma unroll
        for (int j = 0; j < 8; j++)
            #pragma unroll
            for (int k = 0; k < 4; k++) acc[i][j][k] = 0.f;

    // ldmatrix lane addressing: matrix = lane/8; m0: r0-7 c0, m1: r8-15 c0,
    // m2: r0-7 c8, m3: r8-15 c8
    const int mtx = lane >> 3, rr = lane & 7;
    const int lrow = ((mtx & 1) << 3) + rr;
    const int lcol = (mtx & 2) << 2;   // 0 or 8

    const int nch = Kpad >> 5;

    auto load_chunk = [&](int c, int b) {
        uint32_t sbuf = sb + b * BUF_B;
        int k0 = c << 5;
        #pragma unroll
        for (int i = 0; i < 8; i++) {
            int it = i * 256 + tid;          // 0..2047
            int arr = it >> 9;
            int rem = it & 511;
            int row = rem >> 2, ch = rem & 3;
            uint32_t dst = sbuf + arr * ARR_B + row * (ROWP * 2) + ch * 16;
            cp16(dst, gb[arr] + (size_t)row * Kpad + k0 + ch * 8);
        }
        CP_COMMIT();
    };

    auto compute = [&](int b) {
        uint32_t sA_hi = sb + b * BUF_B;
        uint32_t sA_lo = sA_hi + ARR_B;
        uint32_t sB_hi = sA_lo + ARR_B;
        uint32_t sB_lo = sB_hi + ARR_B;
        #pragma unroll
        for (int kk = 0; kk < 2; kk++) {
            int kc = kk * 16;
            uint32_t ah[2][4], al[2][4];
            #pragma unroll
            for (int mi = 0; mi < 2; mi++) {
                uint32_t off = ((warp_m * 32 + mi * 16 + lrow) * ROWP + kc + lcol) * 2;
                ldsm4(ah[mi], sA_hi + off);
                ldsm4(al[mi], sA_lo + off);
            }
            uint32_t bh[4][4], bl[4][4];
            #pragma unroll
            for (int g = 0; g < 4; g++) {
                uint32_t off = ((warp_n * 64 + g * 16 + lrow) * ROWP + kc + lcol) * 2;
                ldsm4(bh[g], sB_hi + off);
                ldsm4(bl[g], sB_lo + off);
            }
            #pragma unroll
            for (int mi = 0; mi < 2; mi++)
                #pragma unroll
                for (int g = 0; g < 4; g++)
                    #pragma unroll
                    for (int s = 0; s < 2; s++) {
                        int j = g * 2 + s;
                        mma_bf16(acc[mi][j], ah[mi], bh[g][s], bh[g][2 + s]);
                        mma_bf16(acc[mi][j], ah[mi], bl[g][s], bl[g][2 + s]);
                        mma_bf16(acc[mi][j], al[mi], bh[g][s], bh[g][2 + s]);
                    }
        }
    };

    load_chunk(0, 0);
    for (int c = 0; c < nch; c++) {
        if (c + 1 < nch) {
            load_chunk(c + 1, (c + 1) & 1);
            CP_WAIT1();
        } else {
            CP_WAIT0();
        }
        __syncthreads();
        compute(c & 1);
        __syncthreads();
    }

    // epilogue: acc c0/c1 -> (row grp, col tig*2 +0/1); c2/c3 -> row+8
    const int grp = lane >> 2, tig = lane & 3;
    const int rb = rowBase + warp_m * 32;
    #pragma unroll
    for (int mi = 0; mi < 2; mi++) {
        #pragma unroll
        for (int j = 0; j < 8; j++) {
            int gc = colBase + warp_n * 64 + j * 8 + tig * 2;
            #pragma unroll
            for (int half = 0; half < 2; half++) {
                int row = rb + mi * 16 + grp + half * 8;
                float v0 = acc[mi][j][half * 2 + 0];
                float v1 = acc[mi][j][half * 2 + 1];
                if (outMode == 0) {
                    float w0 = 0.f, w1 = 0.f;
                    if (gc < Nreal) {
                        w0 = fmaxf(v0 + bias[gc], 0.f);
                        w1 = fmaxf(v1 + bias[gc + 1], 0.f);
                    }
                    __nv_bfloat16 h0 = __float2bfloat16(w0);
                    __nv_bfloat16 h1 = __float2bfloat16(w1);
                    __nv_bfloat16 l0 = __float2bfloat16(w0 - __bfloat162float(h0));
                    __nv_bfloat16 l1 = __float2bfloat16(w1 - __bfloat162float(h1));
                    *(uint32_t*)&outH_hi[(size_t)row * outHStride + gc] = pack_bf2(h0, h1);
                    *(uint32_t*)&outH_lo[(size_t)row * outHStride + gc] = pack_bf2(l0, l1);
                } else {
                    if (row < M && gc < Nreal) {
                        float w0 = v0 + bias[gc];
                        float w1 = v1 + bias[gc + 1];
                        if (doRelu) { w0 = fmaxf(w0, 0.f); w1 = fmaxf(w1, 0.f); }
                        *(float2*)&outF[(size_t)row * outFStride + gc] = make_float2(w0, w1);
                    }
                }
            }
        }
    }
}

// ---------------- SIMT GEMM for small head matmuls ---------------------------
#define GBM 128
#define GBN 128
#define GBK 8
#define APAD 132

__global__ void __launch_bounds__(256, 2)
k_gemm128(const float* __restrict__ A, const float* __restrict__ B,
          const float* __restrict__ bias, float* __restrict__ C,
          int M, int N, int K, int doRelu)
{
    __shared__ float As[2][GBK][APAD];
    __shared__ float Bs[2][GBK][GBN];
    int tid = threadIdx.x;
    int tx = tid & 15, ty = tid >> 4;
    int rowBase = blockIdx.y * GBM, colBase = blockIdx.x * GBN;
    int aRow = tid >> 1, aK = (tid & 1) * 4;
    int bK = tid >> 5, bC = (tid & 31) * 4;

    unsigned long long acc[8][4];
    #pragma unroll
    for (int i = 0; i < 8; i++)
        #pragma unroll
        for (int j = 0; j < 4; j++) acc[i][j] = 0ull;

    int nk = (K + GBK - 1) / GBK;
    float4 aReg = make_float4(0, 0, 0, 0), bReg = make_float4(0, 0, 0, 0);
    {
        int gr = rowBase + aRow;
        if (gr < M && aK < K) aReg = *(const float4*)&A[(size_t)gr * K + aK];
        int gc = colBase + bC;
        if (gc < N && bK < K) bReg = *(const float4*)&B[(size_t)bK * N + gc];
    }
    As[0][aK + 0][aRow] = aReg.x; As[0][aK + 1][aRow] = aReg.y;
    As[0][aK + 2][aRow] = aReg.z; As[0][aK + 3][aRow] = aReg.w;
    *(float4*)&Bs[0][bK][bC] = bReg;
    __syncthreads();

    int buf = 0;
    for (int t = 0; t < nk; t++) {
        int k0n = (t + 1) * GBK;
        aReg = make_float4(0, 0, 0, 0); bReg = make_float4(0, 0, 0, 0);
        {
            int gr = rowBase + aRow, gk = k0n + aK;
            if (gr < M && gk < K) aReg = *(const float4*)&A[(size_t)gr * K + gk];
            int gc = colBase + bC, gkb = k0n + bK;
            if (gc < N && gkb < K) bReg = *(const float4*)&B[(size_t)gkb * N + gc];
        }
        #pragma unroll
        for (int k = 0; k < GBK; k++) {
            const float* asr = &As[buf][k][ty * 8];
            float4 a0 = *(const float4*)asr;
            float4 a1 = *(const float4*)(asr + 4);
            ulonglong2 bA = *(const ulonglong2*)&Bs[buf][k][tx * 8];
            ulonglong2 bB = *(const ulonglong2*)&Bs[buf][k][tx * 8 + 4];
            unsigned long long bv[4] = { bA.x, bA.y, bB.x, bB.y };
            float av[8] = { a0.x, a0.y, a0.z, a0.w, a1.x, a1.y, a1.z, a1.w };
            #pragma unroll
            for (int i = 0; i < 8; i++) {
                unsigned long long ap = bcast2(av[i]);
                #pragma unroll
                for (int j = 0; j < 4; j++) fma2(acc[i][j], ap, bv[j]);
            }
        }
        int nb = buf ^ 1;
        As[nb][aK + 0][aRow] = aReg.x; As[nb][aK + 1][aRow] = aReg.y;
        As[nb][aK + 2][aRow] = aReg.z; As[nb][aK + 3][aRow] = aReg.w;
        *(float4*)&Bs[nb][bK][bC] = bReg;
        __syncthreads();
        buf = nb;
    }

    int gc0 = colBase + tx * 8;
    float bs8[8];
    #pragma unroll
    for (int j = 0; j < 8; j++) bs8[j] = (gc0 + j < N) ? bias[gc0 + j] : 0.f;
    #pragma unroll
    for (int i = 0; i < 8; i++) {
        int gr = rowBase + ty * 8 + i;
        if (gr >= M) continue;
        float v[8];
        #pragma unroll
        for (int jp = 0; jp < 4; jp++) unpack2(acc[i][jp], v[2 * jp], v[2 * jp + 1]);
        #pragma unroll
        for (int j = 0; j < 8; j++) {
            v[j] += bs8[j];
            if (doRelu) v[j] = fmaxf(v[j], 0.f);
        }
        if (gc0 + 7 < N) {
            *(float4*)&C[(size_t)gr * N + gc0]     = make_float4(v[0], v[1], v[2], v[3]);
            *(float4*)&C[(size_t)gr * N + gc0 + 4] = make_float4(v[4], v[5], v[6], v[7]);
        } else {
            #pragma unroll
            for (int j = 0; j < 8; j++)
                if (gc0 + j < N) C[(size_t)gr * N + gc0 + j] = v[j];
        }
    }
}

// ---------------- pooling ----------------------------------------------------
__global__ void k_zero_pool()
{
    int gid = blockIdx.x * blockDim.x + threadIdx.x;
    if (gid < N_GRAPHS_C * EMB) g_pool[gid] = 0.f;
    if (gid < N_GRAPHS_C) g_cnt[gid] = 0;
}

__global__ void k_pool_sum(const int* __restrict__ batch)
{
    int gid = blockIdx.x * blockDim.x + threadIdx.x;
    if (gid >= N_NODES_C * EMB4) return;
    int node = gid / EMB4, q = gid - node * EMB4;
    int g = batch[node];
    float4 v = g_h[gid];
    float* dst = &g_pool[g * EMB + q * 4];
    atomicAdd(dst + 0, v.x); atomicAdd(dst + 1, v.y);
    atomicAdd(dst + 2, v.z); atomicAdd(dst + 3, v.w);
}

__global__ void k_pool_cnt(const int* __restrict__ batch)
{
    int gid = blockIdx.x * blockDim.x + threadIdx.x;
    if (gid >= N_NODES_C) return;
    atomicAdd(&g_cnt[batch[gid]], 1);
}

__global__ void k_pool_mean()
{
    int gid = blockIdx.x * blockDim.x + threadIdx.x;
    if (gid >= N_GRAPHS_C * EMB) return;
    int g = gid / EMB;
    int c = g_cnt[g];
    g_hg[gid] = g_pool[gid] / ((c > 0) ? (float)c : 1.f);
}

// ---------------- launch -----------------------------------------------------
extern "C" void kernel_launch(void* const* d_in, const int* in_sizes, int n_in,
                              void* d_out, int out_size)
{
    const int*   x          = (const int*)  d_in[0];
    const int*   edge_index = (const int*)  d_in[1];
    const int*   edge_attr  = (const int*)  d_in[2];
    const int*   batch      = (const int*)  d_in[3];
    const float* x_emb1     = (const float*)d_in[4];
    const float* x_emb2     = (const float*)d_in[5];
    const float* edge_e1    = (const float*)d_in[6];
    const float* edge_e2    = (const float*)d_in[7];
    const float* W1         = (const float*)d_in[8];
    const float* b1         = (const float*)d_in[9];
    const float* W2         = (const float*)d_in[10];
    const float* b2         = (const float*)d_in[11];
    const float* feat_W     = (const float*)d_in[12];
    const float* feat_b     = (const float*)d_in[13];
    const float* p0_W       = (const float*)d_in[14];
    const float* p0_b       = (const float*)d_in[15];
    const float* p1_W       = (const float*)d_in[16];
    const float* p1_b       = (const float*)d_in[17];
    const float* p2_W       = (const float*)d_in[18];
    const float* p2_b       = (const float*)d_in[19];

    float* out_hg   = (float*)d_out;
    float* out_proj = (float*)d_out + N_GRAPHS_C * FEAT;

    const int T = 256;
    const int nodeElems = N_NODES_C * EMB4;

    static float *p_h = nullptr, *p_hg = nullptr, *p_p = nullptr, *p_pb = nullptr;
    static __nv_bfloat16 *p_ah = nullptr, *p_al = nullptr, *p_th = nullptr, *p_tl = nullptr,
                         *p_w1h = nullptr, *p_w1l = nullptr, *p_w2h = nullptr, *p_w2l = nullptr;
    if (!p_h) {
        void* t;
        cudaGetSymbolAddress(&t, g_h);       p_h   = (float*)t;
        cudaGetSymbolAddress(&t, g_hg);      p_hg  = (float*)t;
        cudaGetSymbolAddress(&t, g_p);       p_p   = (float*)t;
        cudaGetSymbolAddress(&t, g_pb);      p_pb  = (float*)t;
        cudaGetSymbolAddress(&t, g_aggr_hi); p_ah  = (__nv_bfloat16*)t;
        cudaGetSymbolAddress(&t, g_aggr_lo); p_al  = (__nv_bfloat16*)t;
        cudaGetSymbolAddress(&t, g_tmp_hi);  p_th  = (__nv_bfloat16*)t;
        cudaGetSymbolAddress(&t, g_tmp_lo);  p_tl  = (__nv_bfloat16*)t;
        cudaGetSymbolAddress(&t, g_w1t_hi);  p_w1h = (__nv_bfloat16*)t;
        cudaGetSymbolAddress(&t, g_w1t_lo);  p_w1l = (__nv_bfloat16*)t;
        cudaGetSymbolAddress(&t, g_w2t_hi);  p_w2h = (__nv_bfloat16*)t;
        cudaGetSymbolAddress(&t, g_w2t_lo);  p_w2l = (__nv_bfloat16*)t;
        cudaFuncSetAttribute(k_mma_gemm, cudaFuncAttributeMaxDynamicSharedMemorySize,
                             MMA_SMEM);
    }

    // 1. initial node embedding
    k_init_h<<<(nodeElems + T - 1) / T, T>>>(x, (const float4*)x_emb1,
                                             (const float4*)x_emb2);

    // 2. CSR build
    k_zero_deg<<<(N_NODES_C + T - 1) / T, T>>>();
    k_hist<<<(N_EDGES_C + T - 1) / T, T>>>(edge_index);
    k_scan<<<1, 1024>>>();
    k_fill<<<(N_EDGES_C + T - 1) / T, T>>>(edge_index, edge_attr);

    const int Mtiles = (N_NODES_C + 127) / 128;   // 391

    // 3. GINE layers
    for (int l = 0; l < NLAYER; l++) {
        const float* e1l = edge_e1 + l * 5 * EMB;
        const float* e2l = edge_e2 + l * 3 * EMB;

        k_combo<<<(15 * EMB4 + T - 1) / T, T>>>((const float4*)e1l,
                                                (const float4*)e2l);
        k_gather<<<N_NODES_C, 96>>>();

        k_convW<<<(W1T_ROWS * K1PAD + T - 1) / T, T>>>(W1 + l * EMB * HID,
                                                       p_w1h, p_w1l, EMB, HID,
                                                       K1PAD, W1T_ROWS);
        k_convW<<<(W2T_ROWS * K2PAD + T - 1) / T, T>>>(W2 + l * HID * EMB,
                                                       p_w2h, p_w2l, HID, EMB,
                                                       K2PAD, W2T_ROWS);

        // GEMM1: tmp = relu(aggr @ W1 + b1) -> split bf16 [*, 640]
        {
            dim3 grid(W1T_ROWS / 128, Mtiles);
            k_mma_gemm<<<grid, 256, MMA_SMEM>>>(p_ah, p_al, p_w1h, p_w1l,
                                                b1 + l * HID,
                                                N_NODES_C, HID, K1PAD,
                                                nullptr, 0, p_th, p_tl, K2PAD, 0, 1);
        }
        // GEMM2: h = tmp @ W2 + b2 (+relu) -> fp32 [*, 300]
        {
            dim3 grid(W2T_ROWS / 128, Mtiles);
            k_mma_gemm<<<grid, 256, MMA_SMEM>>>(p_th, p_tl, p_w2h, p_w2l,
                                                b2 + l * EMB,
                                                N_NODES_C, EMB, K2PAD,
                                                p_h, EMB, nullptr, nullptr, 0, 1,
                                                (l < NLAYER - 1) ? 1 : 0);
        }
    }

    // 4. global mean pool
    k_zero_pool<<<(N_GRAPHS_C * EMB + T - 1) / T, T>>>();
    k_pool_sum<<<(nodeElems + T - 1) / T, T>>>(batch);
    k_pool_cnt<<<(N_NODES_C + T - 1) / T, T>>>(batch);
    k_pool_mean<<<(N_GRAPHS_C * EMB + T - 1) / T, T>>>();

    // 5. feat_lin + pred head (SIMT GEMM, small M)
    {
        dim3 grid((FEAT + GBN - 1) / GBN, (N_GRAPHS_C + GBM - 1) / GBM);
        k_gemm128<<<grid, 256>>>(p_hg, feat_W, feat_b, out_hg,
                                 N_GRAPHS_C, FEAT, EMB, 0);
    }
    {
        dim3 grid((FEAT / 2 + GBN - 1) / GBN, (N_GRAPHS_C + GBM - 1) / GBM);
        k_gemm128<<<grid, 256>>>(out_hg, p0_W, p0_b, p_p,
                                 N_GRAPHS_C, FEAT / 2, FEAT, 1);
        k_gemm128<<<grid, 256>>>(p_p, p1_W, p1_b, p_pb,
                                 N_GRAPHS_C, FEAT / 2, FEAT / 2, 1);
    }
    {
        dim3 grid((OUTD + GBN - 1) / GBN, (N_GRAPHS_C + GBM - 1) / GBM);
        k_gemm128<<<grid, 256>>>(p_pb, p2_W, p2_b, out_proj,
                                 N_GRAPHS_C, OUTD, FEAT / 2, 0);
    }
}

// round 5
// speedup vs baseline: 3.9712x; 1.2460x over previous
#include <cuda_runtime.h>
#include <cuda_bf16.h>
#include <cstdint>

#define N_NODES_C  50000
#define N_EDGES_C  800000
#define N_GRAPHS_C 2000
#define EMB   300
#define EMB4  75
#define HID   600
#define FEAT  512
#define OUTD  256
#define NLAYER 5

#define MROWS_PAD 50048          // 391 * 128
#define K1PAD 320
#define K2PAD 640
#define W1T_ROWS 640
#define W2T_ROWS 384
#define SCANB 196                // ceil(50000/256)

// ---------------- scratch ----------------------------------------------------
__device__ float4 g_h[N_NODES_C * EMB4];
__device__ __nv_bfloat16 g_aggr_hi[MROWS_PAD * K1PAD];
__device__ __nv_bfloat16 g_aggr_lo[MROWS_PAD * K1PAD];
__device__ __nv_bfloat16 g_tmp_hi[(size_t)MROWS_PAD * K2PAD];
__device__ __nv_bfloat16 g_tmp_lo[(size_t)MROWS_PAD * K2PAD];
__device__ __nv_bfloat16 g_w1t_hi[W1T_ROWS * K1PAD];
__device__ __nv_bfloat16 g_w1t_lo[W1T_ROWS * K1PAD];
__device__ __nv_bfloat16 g_w2t_hi[W2T_ROWS * K2PAD];
__device__ __nv_bfloat16 g_w2t_lo[W2T_ROWS * K2PAD];
__device__ float  g_hg[N_GRAPHS_C * EMB];
__device__ float  g_p[N_GRAPHS_C * (FEAT/2)];
__device__ float  g_pb[N_GRAPHS_C * (FEAT/2)];
__device__ int    g_deg[N_NODES_C];
__device__ int    g_rowptr[N_NODES_C];
__device__ int    g_cursor[N_NODES_C];
__device__ int    g_csr[N_EDGES_C];
__device__ float4 g_ee[15 * EMB4];
__device__ int    g_bsum[SCANB];
__device__ int    g_boff[SCANB];
__device__ int    g_gs[N_GRAPHS_C];
__device__ int    g_ge[N_GRAPHS_C];

// ---------------- PTX helpers -------------------------------------------------
__device__ __forceinline__ uint32_t smem_u32(const void* p) {
    uint32_t a;
    asm("{ .reg .u64 t; cvta.to.shared.u64 t, %1; cvt.u32.u64 %0, t; }" : "=r"(a) : "l"(p));
    return a;
}
__device__ __forceinline__ void cp16(uint32_t saddr, const void* g) {
    asm volatile("cp.async.cg.shared.global [%0], [%1], 16;" :: "r"(saddr), "l"(g));
}
#define CP_COMMIT() asm volatile("cp.async.commit_group;" ::: "memory")
#define CP_WAIT1()  asm volatile("cp.async.wait_group 1;" ::: "memory")
#define CP_WAIT0()  asm volatile("cp.async.wait_group 0;" ::: "memory")

__device__ __forceinline__ void ldsm4(uint32_t* f, uint32_t addr) {
    asm volatile("ldmatrix.sync.aligned.m8n8.x4.shared.b16 {%0,%1,%2,%3}, [%4];"
        : "=r"(f[0]), "=r"(f[1]), "=r"(f[2]), "=r"(f[3]) : "r"(addr));
}
__device__ __forceinline__ void mma_bf16(float* c, const uint32_t* a,
                                         uint32_t b0, uint32_t b1) {
    asm volatile("mma.sync.aligned.m16n8k16.row.col.f32.bf16.bf16.f32 "
        "{%0,%1,%2,%3}, {%4,%5,%6,%7}, {%8,%9}, {%0,%1,%2,%3};"
        : "+f"(c[0]), "+f"(c[1]), "+f"(c[2]), "+f"(c[3])
        : "r"(a[0]), "r"(a[1]), "r"(a[2]), "r"(a[3]), "r"(b0), "r"(b1));
}
__device__ __forceinline__ uint32_t pack_bf2(__nv_bfloat16 a, __nv_bfloat16 b) {
    __nv_bfloat162 t; t.x = a; t.y = b;
    return *(uint32_t*)&t;
}
__device__ __forceinline__ void fma2(unsigned long long& d, unsigned long long a,
                                     unsigned long long b) {
    asm("fma.rn.f32x2 %0, %1, %2, %0;" : "+l"(d) : "l"(a), "l"(b));
}
__device__ __forceinline__ unsigned long long bcast2(float a) {
    unsigned long long r; unsigned u = __float_as_uint(a);
    asm("mov.b64 %0, {%1, %1};" : "=l"(r) : "r"(u));
    return r;
}
__device__ __forceinline__ void unpack2(unsigned long long v, float& lo, float& hi) {
    unsigned a, b;
    asm("mov.b64 {%0, %1}, %2;" : "=r"(a), "=r"(b) : "l"(v));
    lo = __uint_as_float(a); hi = __uint_as_float(b);
}

// ---------------- small kernels ----------------------------------------------
__global__ void k_init_h(const int* __restrict__ x,
                         const float4* __restrict__ emb1,
                         const float4* __restrict__ emb2)
{
    int gid = blockIdx.x * blockDim.x + threadIdx.x;
    if (gid >= N_NODES_C * EMB4) return;
    int node = gid / EMB4, q = gid - node * EMB4;
    float4 a = emb1[x[node * 2 + 0] * EMB4 + q];
    float4 b = emb2[x[node * 2 + 1] * EMB4 + q];
    float4 r; r.x = a.x + b.x; r.y = a.y + b.y; r.z = a.z + b.z; r.w = a.w + b.w;
    g_h[gid] = r;
}

__global__ void k_zero_deg()
{
    int gid = blockIdx.x * blockDim.x + threadIdx.x;
    if (gid < N_NODES_C) g_deg[gid] = 0;
}

__global__ void k_hist(const int* __restrict__ edge_index)
{
    int e = blockIdx.x * blockDim.x + threadIdx.x;
    if (e >= N_EDGES_C) return;
    atomicAdd(&g_deg[edge_index[N_EDGES_C + e]], 1);
}

// ---- 3-stage scan ----
__global__ void k_scan1()   // grid SCANB, block 256: block sums of deg
{
    __shared__ int s[256];
    int t = threadIdx.x;
    int i = blockIdx.x * 256 + t;
    int v = (i < N_NODES_C) ? g_deg[i] : 0;
    s[t] = v;
    __syncthreads();
    for (int off = 128; off > 0; off >>= 1) {
        if (t < off) s[t] += s[t + off];
        __syncthreads();
    }
    if (t == 0) g_bsum[blockIdx.x] = s[0];
}

__global__ void k_scan2()   // 1 block 256: exclusive scan of partials
{
    __shared__ int s[256];
    int t = threadIdx.x;
    int v = (t < SCANB) ? g_bsum[t] : 0;
    s[t] = v;
    __syncthreads();
    for (int off = 1; off < 256; off <<= 1) {
        int x = (t >= off) ? s[t - off] : 0;
        __syncthreads();
        s[t] += x;
        __syncthreads();
    }
    if (t < SCANB) g_boff[t] = s[t] - v;
}

__global__ void k_scan3()   // grid SCANB, block 256: local scan + offset
{
    __shared__ int s[256];
    int t = threadIdx.x;
    int i = blockIdx.x * 256 + t;
    int v = (i < N_NODES_C) ? g_deg[i] : 0;
    s[t] = v;
    __syncthreads();
    for (int off = 1; off < 256; off <<= 1) {
        int x = (t >= off) ? s[t - off] : 0;
        __syncthreads();
        s[t] += x;
        __syncthreads();
    }
    if (i < N_NODES_C) {
        int excl = s[t] - v + g_boff[blockIdx.x];
        g_rowptr[i] = excl;
        g_cursor[i] = excl;
    }
}

__global__ void k_fill(const int* __restrict__ edge_index,
                       const int* __restrict__ edge_attr)
{
    int e = blockIdx.x * blockDim.x + threadIdx.x;
    if (e >= N_EDGES_C) return;
    int dst = edge_index[N_EDGES_C + e];
    int src = edge_index[e];
    int a0 = edge_attr[2 * e + 0], a1 = edge_attr[2 * e + 1];
    int pos = atomicAdd(&g_cursor[dst], 1);
    g_csr[pos] = src | ((a0 * 3 + a1) << 16);
}

__global__ void k_combo(const float4* __restrict__ e1, const float4* __restrict__ e2)
{
    int gid = blockIdx.x * blockDim.x + threadIdx.x;
    if (gid >= 15 * EMB4) return;
    int c = gid / EMB4, q = gid - c * EMB4;
    float4 a = e1[(c / 3) * EMB4 + q];
    float4 b = e2[(c % 3) * EMB4 + q];
    float4 r; r.x = a.x + b.x; r.y = a.y + b.y; r.z = a.z + b.z; r.w = a.w + b.w;
    g_ee[gid] = r;
}

// gather -> split bf16 aggr, zero-padded to K1PAD
__global__ void k_gather()
{
    int node = blockIdx.x;
    int q = threadIdx.x;
    if (q >= 80) return;
    __nv_bfloat16* dst_hi = &g_aggr_hi[(size_t)node * K1PAD + q * 4];
    __nv_bfloat16* dst_lo = &g_aggr_lo[(size_t)node * K1PAD + q * 4];
    if (q >= EMB4) {
        *(uint2*)dst_hi = make_uint2(0, 0);
        *(uint2*)dst_lo = make_uint2(0, 0);
        return;
    }
    float4 acc = g_h[node * EMB4 + q];
    float4 sl = g_ee[12 * EMB4 + q];
    acc.x += sl.x; acc.y += sl.y; acc.z += sl.z; acc.w += sl.w;
    int s = g_rowptr[node];
    int e = s + g_deg[node];
    int p = s;
    for (; p + 1 < e; p += 2) {
        int pk0 = g_csr[p], pk1 = g_csr[p + 1];
        int s0 = pk0 & 0xffff, c0 = pk0 >> 16;
        int s1 = pk1 & 0xffff, c1 = pk1 >> 16;
        float4 h0 = g_h[s0 * EMB4 + q];
        float4 e0 = g_ee[c0 * EMB4 + q];
        float4 h1 = g_h[s1 * EMB4 + q];
        float4 e1 = g_ee[c1 * EMB4 + q];
        acc.x += (h0.x + e0.x) + (h1.x + e1.x);
        acc.y += (h0.y + e0.y) + (h1.y + e1.y);
        acc.z += (h0.z + e0.z) + (h1.z + e1.z);
        acc.w += (h0.w + e0.w) + (h1.w + e1.w);
    }
    if (p < e) {
        int pk = g_csr[p];
        int s0 = pk & 0xffff, c0 = pk >> 16;
        float4 h0 = g_h[s0 * EMB4 + q];
        float4 e0 = g_ee[c0 * EMB4 + q];
        acc.x += h0.x + e0.x; acc.y += h0.y + e0.y;
        acc.z += h0.z + e0.z; acc.w += h0.w + e0.w;
    }
    float v[4] = { acc.x, acc.y, acc.z, acc.w };
    __nv_bfloat16 hi[4], lo[4];
    #pragma unroll
    for (int i = 0; i < 4; i++) {
        hi[i] = __float2bfloat16(v[i]);
        lo[i] = __float2bfloat16(v[i] - __bfloat162float(hi[i]));
    }
    *(uint2*)dst_hi = *(uint2*)hi;
    *(uint2*)dst_lo = *(uint2*)lo;
}

// W [K,N] fp32 -> WT split [Npad, Kpad] bf16 — coalesced smem transpose.
// grid (Npad/32, Kpad/32), block (32, 8). Npad, Kpad multiples of 32.
__global__ void k_convW_t(const float* __restrict__ W,
                          __nv_bfloat16* __restrict__ T_hi,
                          __nv_bfloat16* __restrict__ T_lo,
                          int K, int N, int Kpad)
{
    __shared__ float tile[32][33];
    int n0 = blockIdx.x * 32, k0 = blockIdx.y * 32;
    int tx = threadIdx.x, ty = threadIdx.y;
    #pragma unroll
    for (int i = 0; i < 4; i++) {
        int k = k0 + ty + i * 8, n = n0 + tx;
        tile[ty + i * 8][tx] = (k < K && n < N) ? W[(size_t)k * N + n] : 0.f;
    }
    __syncthreads();
    #pragma unroll
    for (int i = 0; i < 4; i++) {
        int n = n0 + ty + i * 8, k = k0 + tx;
        float v = tile[tx][ty + i * 8];
        __nv_bfloat16 h = __float2bfloat16(v);
        T_hi[(size_t)n * Kpad + k] = h;
        T_lo[(size_t)n * Kpad + k] = __float2bfloat16(v - __bfloat162float(h));
    }
}

// ---------------- split-bf16 mma.sync GEMM -----------------------------------
#define ROWP 40
#define ARR_B (128 * ROWP * 2)
#define BUF_B (4 * ARR_B)
#define MMA_SMEM (2 * BUF_B)

__global__ void __launch_bounds__(256, 2)
k_mma_gemm(const __nv_bfloat16* __restrict__ A_hi, const __nv_bfloat16* __restrict__ A_lo,
           const __nv_bfloat16* __restrict__ B_hi, const __nv_bfloat16* __restrict__ B_lo,
           const float* __restrict__ bias,
           int M, int Nreal, int Kpad,
           float* __restrict__ outF, int outFStride,
           __nv_bfloat16* __restrict__ outH_hi, __nv_bfloat16* __restrict__ outH_lo,
           int outHStride, int outMode, int doRelu)
{
    extern __shared__ char smem[];
    const int tid = threadIdx.x;
    const int lane = tid & 31, wid = tid >> 5;
    const int warp_m = wid & 3, warp_n = wid >> 2;
    const int rowBase = blockIdx.y * 128, colBase = blockIdx.x * 128;
    uint32_t sb = smem_u32(smem);

    const __nv_bfloat16* gb[4] = {
        A_hi + (size_t)rowBase * Kpad, A_lo + (size_t)rowBase * Kpad,
        B_hi + (size_t)colBase * Kpad, B_lo + (size_t)colBase * Kpad };

    float acc[2][8][4];
    #pragma unroll
    for (int i = 0; i < 2; i++)
        #pragma unroll
        for (int j = 0; j < 8; j++)
            #pragma unroll
            for (int k = 0; k < 4; k++) acc[i][j][k] = 0.f;

    const int mtx = lane >> 3, rr = lane & 7;
    const int lrow = ((mtx & 1) << 3) + rr;
    const int lcol = (mtx & 2) << 2;

    const int nch = Kpad >> 5;

    auto load_chunk = [&](int c, int b) {
        uint32_t sbuf = sb + b * BUF_B;
        int k0 = c << 5;
        #pragma unroll
        for (int i = 0; i < 8; i++) {
            int it = i * 256 + tid;
            int arr = it >> 9;
            int rem = it & 511;
            int row = rem >> 2, ch = rem & 3;
            uint32_t dst = sbuf + arr * ARR_B + row * (ROWP * 2) + ch * 16;
            cp16(dst, gb[arr] + (size_t)row * Kpad + k0 + ch * 8);
        }
        CP_COMMIT();
    };

    auto compute = [&](int b) {
        uint32_t sA_hi = sb + b * BUF_B;
        uint32_t sA_lo = sA_hi + ARR_B;
        uint32_t sB_hi = sA_lo + ARR_B;
        uint32_t sB_lo = sB_hi + ARR_B;
        #pragma unroll
        for (int kk = 0; kk < 2; kk++) {
            int kc = kk * 16;
            uint32_t ah[2][4], al[2][4];
            #pragma unroll
            for (int mi = 0; mi < 2; mi++) {
                uint32_t off = ((warp_m * 32 + mi * 16 + lrow) * ROWP + kc + lcol) * 2;
                ldsm4(ah[mi], sA_hi + off);
                ldsm4(al[mi], sA_lo + off);
            }
            #pragma unroll
            for (int g = 0; g < 4; g++) {
                uint32_t bh4[4], bl4[4];
                uint32_t off = ((warp_n * 64 + g * 16 + lrow) * ROWP + kc + lcol) * 2;
                ldsm4(bh4, sB_hi + off);
                ldsm4(bl4, sB_lo + off);
                #pragma unroll
                for (int mi = 0; mi < 2; mi++)
                    #pragma unroll
                    for (int s = 0; s < 2; s++) {
                        int j = g * 2 + s;
                        mma_bf16(acc[mi][j], ah[mi], bh4[s], bh4[2 + s]);
                        mma_bf16(acc[mi][j], ah[mi], bl4[s], bl4[2 + s]);
                        mma_bf16(acc[mi][j], al[mi], bh4[s], bh4[2 + s]);
                    }
            }
        }
    };

    load_chunk(0, 0);
    for (int c = 0; c < nch; c++) {
        if (c + 1 < nch) {
            load_chunk(c + 1, (c + 1) & 1);
            CP_WAIT1();
        } else {
            CP_WAIT0();
        }
        __syncthreads();
        compute(c & 1);
        __syncthreads();
    }

    const int grp = lane >> 2, tig = lane & 3;
    const int rb = rowBase + warp_m * 32;
    #pragma unroll
    for (int mi = 0; mi < 2; mi++) {
        #pragma unroll
        for (int j = 0; j < 8; j++) {
            int gc = colBase + warp_n * 64 + j * 8 + tig * 2;
            #pragma unroll
            for (int half = 0; half < 2; half++) {
                int row = rb + mi * 16 + grp + half * 8;
                float v0 = acc[mi][j][half * 2 + 0];
                float v1 = acc[mi][j][half * 2 + 1];
                if (outMode == 0) {
                    float w0 = 0.f, w1 = 0.f;
                    if (gc < Nreal) {
                        w0 = fmaxf(v0 + bias[gc], 0.f);
                        w1 = fmaxf(v1 + bias[gc + 1], 0.f);
                    }
                    __nv_bfloat16 h0 = __float2bfloat16(w0);
                    __nv_bfloat16 h1 = __float2bfloat16(w1);
                    __nv_bfloat16 l0 = __float2bfloat16(w0 - __bfloat162float(h0));
                    __nv_bfloat16 l1 = __float2bfloat16(w1 - __bfloat162float(h1));
                    *(uint32_t*)&outH_hi[(size_t)row * outHStride + gc] = pack_bf2(h0, h1);
                    *(uint32_t*)&outH_lo[(size_t)row * outHStride + gc] = pack_bf2(l0, l1);
                } else {
                    if (row < M && gc < Nreal) {
                        float w0 = v0 + bias[gc];
                        float w1 = v1 + bias[gc + 1];
                        if (doRelu) { w0 = fmaxf(w0, 0.f); w1 = fmaxf(w1, 0.f); }
                        *(float2*)&outF[(size_t)row * outFStride + gc] = make_float2(w0, w1);
                    }
                }
            }
        }
    }
}

// ---------------- SIMT GEMM (heads) ------------------------------------------
#define GBM 128
#define GBN 128
#define GBK 8
#define APAD 132

__global__ void __launch_bounds__(256, 2)
k_gemm128(const float* __restrict__ A, const float* __restrict__ B,
          const float* __restrict__ bias, float* __restrict__ C,
          int M, int N, int K, int doRelu)
{
    __shared__ float As[2][GBK][APAD];
    __shared__ float Bs[2][GBK][GBN];
    int tid = threadIdx.x;
    int tx = tid & 15, ty = tid >> 4;
    int rowBase = blockIdx.y * GBM, colBase = blockIdx.x * GBN;
    int aRow = tid >> 1, aK = (tid & 1) * 4;
    int bK = tid >> 5, bC = (tid & 31) * 4;

    unsigned long long acc[8][4];
    #pragma unroll
    for (int i = 0; i < 8; i++)
        #pragma unroll
        for (int j = 0; j < 4; j++) acc[i][j] = 0ull;

    int nk = (K + GBK - 1) / GBK;
    float4 aReg = make_float4(0, 0, 0, 0), bReg = make_float4(0, 0, 0, 0);
    {
        int gr = rowBase + aRow;
        if (gr < M && aK < K) aReg = *(const float4*)&A[(size_t)gr * K + aK];
        int gc = colBase + bC;
        if (gc < N && bK < K) bReg = *(const float4*)&B[(size_t)bK * N + gc];
    }
    As[0][aK + 0][aRow] = aReg.x; As[0][aK + 1][aRow] = aReg.y;
    As[0][aK + 2][aRow] = aReg.z; As[0][aK + 3][aRow] = aReg.w;
    *(float4*)&Bs[0][bK][bC] = bReg;
    __syncthreads();

    int buf = 0;
    for (int t = 0; t < nk; t++) {
        int k0n = (t + 1) * GBK;
        aReg = make_float4(0, 0, 0, 0); bReg = make_float4(0, 0, 0, 0);
        {
            int gr = rowBase + aRow, gk = k0n + aK;
            if (gr < M && gk < K) aReg = *(const float4*)&A[(size_t)gr * K + gk];
            int gc = colBase + bC, gkb = k0n + bK;
            if (gc < N && gkb < K) bReg = *(const float4*)&B[(size_t)gkb * N + gc];
        }
        #pragma unroll
        for (int k = 0; k < GBK; k++) {
            const float* asr = &As[buf][k][ty * 8];
            float4 a0 = *(const float4*)asr;
            float4 a1 = *(const float4*)(asr + 4);
            ulonglong2 bA = *(const ulonglong2*)&Bs[buf][k][tx * 8];
            ulonglong2 bB = *(const ulonglong2*)&Bs[buf][k][tx * 8 + 4];
            unsigned long long bv[4] = { bA.x, bA.y, bB.x, bB.y };
            float av[8] = { a0.x, a0.y, a0.z, a0.w, a1.x, a1.y, a1.z, a1.w };
            #pragma unroll
            for (int i = 0; i < 8; i++) {
                unsigned long long ap = bcast2(av[i]);
                #pragma unroll
                for (int j = 0; j < 4; j++) fma2(acc[i][j], ap, bv[j]);
            }
        }
        int nb = buf ^ 1;
        As[nb][aK + 0][aRow] = aReg.x; As[nb][aK + 1][aRow] = aReg.y;
        As[nb][aK + 2][aRow] = aReg.z; As[nb][aK + 3][aRow] = aReg.w;
        *(float4*)&Bs[nb][bK][bC] = bReg;
        __syncthreads();
        buf = nb;
    }

    int gc0 = colBase + tx * 8;
    float bs8[8];
    #pragma unroll
    for (int j = 0; j < 8; j++) bs8[j] = (gc0 + j < N) ? bias[gc0 + j] : 0.f;
    #pragma unroll
    for (int i = 0; i < 8; i++) {
        int gr = rowBase + ty * 8 + i;
        if (gr >= M) continue;
        float v[8];
        #pragma unroll
        for (int jp = 0; jp < 4; jp++) unpack2(acc[i][jp], v[2 * jp], v[2 * jp + 1]);
        #pragma unroll
        for (int j = 0; j < 8; j++) {
            v[j] += bs8[j];
            if (doRelu) v[j] = fmaxf(v[j], 0.f);
        }
        if (gc0 + 7 < N) {
            *(float4*)&C[(size_t)gr * N + gc0]     = make_float4(v[0], v[1], v[2], v[3]);
            *(float4*)&C[(size_t)gr * N + gc0 + 4] = make_float4(v[4], v[5], v[6], v[7]);
        } else {
            #pragma unroll
            for (int j = 0; j < 8; j++)
                if (gc0 + j < N) C[(size_t)gr * N + gc0 + j] = v[j];
        }
    }
}

// ---------------- segment pooling (batch is sorted) ---------------------------
__global__ void k_gb_init()
{
    int g = blockIdx.x * blockDim.x + threadIdx.x;
    if (g < N_GRAPHS_C) { g_gs[g] = 0; g_ge[g] = 0; }
}

__global__ void k_gbounds(const int* __restrict__ batch)
{
    int i = blockIdx.x * blockDim.x + threadIdx.x;
    if (i >= N_NODES_C) return;
    int b = batch[i];
    if (i == 0 || batch[i - 1] != b) g_gs[b] = i;
    if (i == N_NODES_C - 1 || batch[i + 1] != b) g_ge[b] = i + 1;
}

__global__ void k_pool_seg()   // grid N_GRAPHS, block 96
{
    int g = blockIdx.x;
    int q = threadIdx.x;
    if (q >= EMB4) return;
    int s = g_gs[g], e = g_ge[g];
    float4 acc = make_float4(0.f, 0.f, 0.f, 0.f);
    for (int r = s; r < e; r++) {
        float4 v = g_h[r * EMB4 + q];
        acc.x += v.x; acc.y += v.y; acc.z += v.z; acc.w += v.w;
    }
    float inv = 1.f / ((e > s) ? (float)(e - s) : 1.f);
    float4 o; o.x = acc.x * inv; o.y = acc.y * inv; o.z = acc.z * inv; o.w = acc.w * inv;
    *(float4*)&g_hg[g * EMB + q * 4] = o;
}

// ---------------- launch -----------------------------------------------------
extern "C" void kernel_launch(void* const* d_in, const int* in_sizes, int n_in,
                              void* d_out, int out_size)
{
    const int*   x          = (const int*)  d_in[0];
    const int*   edge_index = (const int*)  d_in[1];
    const int*   edge_attr  = (const int*)  d_in[2];
    const int*   batch      = (const int*)  d_in[3];
    const float* x_emb1     = (const float*)d_in[4];
    const float* x_emb2     = (const float*)d_in[5];
    const float* edge_e1    = (const float*)d_in[6];
    const float* edge_e2    = (const float*)d_in[7];
    const float* W1         = (const float*)d_in[8];
    const float* b1         = (const float*)d_in[9];
    const float* W2         = (const float*)d_in[10];
    const float* b2         = (const float*)d_in[11];
    const float* feat_W     = (const float*)d_in[12];
    const float* feat_b     = (const float*)d_in[13];
    const float* p0_W       = (const float*)d_in[14];
    const float* p0_b       = (const float*)d_in[15];
    const float* p1_W       = (const float*)d_in[16];
    const float* p1_b       = (const float*)d_in[17];
    const float* p2_W       = (const float*)d_in[18];
    const float* p2_b       = (const float*)d_in[19];

    float* out_hg   = (float*)d_out;
    float* out_proj = (float*)d_out + N_GRAPHS_C * FEAT;

    const int T = 256;
    const int nodeElems = N_NODES_C * EMB4;

    static float *p_h = nullptr, *p_hg = nullptr, *p_p = nullptr, *p_pb = nullptr;
    static __nv_bfloat16 *p_ah = nullptr, *p_al = nullptr, *p_th = nullptr, *p_tl = nullptr,
                         *p_w1h = nullptr, *p_w1l = nullptr, *p_w2h = nullptr, *p_w2l = nullptr;
    if (!p_h) {
        void* t;
        cudaGetSymbolAddress(&t, g_h);       p_h   = (float*)t;
        cudaGetSymbolAddress(&t, g_hg);      p_hg  = (float*)t;
        cudaGetSymbolAddress(&t, g_p);       p_p   = (float*)t;
        cudaGetSymbolAddress(&t, g_pb);      p_pb  = (float*)t;
        cudaGetSymbolAddress(&t, g_aggr_hi); p_ah  = (__nv_bfloat16*)t;
        cudaGetSymbolAddress(&t, g_aggr_lo); p_al  = (__nv_bfloat16*)t;
        cudaGetSymbolAddress(&t, g_tmp_hi);  p_th  = (__nv_bfloat16*)t;
        cudaGetSymbolAddress(&t, g_tmp_lo);  p_tl  = (__nv_bfloat16*)t;
        cudaGetSymbolAddress(&t, g_w1t_hi);  p_w1h = (__nv_bfloat16*)t;
        cudaGetSymbolAddress(&t, g_w1t_lo);  p_w1l = (__nv_bfloat16*)t;
        cudaGetSymbolAddress(&t, g_w2t_hi);  p_w2h = (__nv_bfloat16*)t;
        cudaGetSymbolAddress(&t, g_w2t_lo);  p_w2l = (__nv_bfloat16*)t;
        cudaFuncSetAttribute(k_mma_gemm, cudaFuncAttributeMaxDynamicSharedMemorySize,
                             MMA_SMEM);
    }

    // 1. initial node embedding
    k_init_h<<<(nodeElems + T - 1) / T, T>>>(x, (const float4*)x_emb1,
                                             (const float4*)x_emb2);

    // 2. CSR build
    k_zero_deg<<<(N_NODES_C + T - 1) / T, T>>>();
    k_hist<<<(N_EDGES_C + T - 1) / T, T>>>(edge_index);
    k_scan1<<<SCANB, 256>>>();
    k_scan2<<<1, 256>>>();
    k_scan3<<<SCANB, 256>>>();
    k_fill<<<(N_EDGES_C + T - 1) / T, T>>>(edge_index, edge_attr);

    // graph bounds (independent; compute once)
    k_gb_init<<<(N_GRAPHS_C + T - 1) / T, T>>>();
    k_gbounds<<<(N_NODES_C + T - 1) / T, T>>>(batch);

    const int Mtiles = (N_NODES_C + 127) / 128;   // 391

    // 3. GINE layers
    for (int l = 0; l < NLAYER; l++) {
        const float* e1l = edge_e1 + l * 5 * EMB;
        const float* e2l = edge_e2 + l * 3 * EMB;

        k_combo<<<(15 * EMB4 + T - 1) / T, T>>>((const float4*)e1l,
                                                (const float4*)e2l);
        k_gather<<<N_NODES_C, 96>>>();

        {
            dim3 blk(32, 8);
            dim3 g1(W1T_ROWS / 32, K1PAD / 32);
            k_convW_t<<<g1, blk>>>(W1 + l * EMB * HID, p_w1h, p_w1l, EMB, HID, K1PAD);
            dim3 g2(W2T_ROWS / 32, K2PAD / 32);
            k_convW_t<<<g2, blk>>>(W2 + l * HID * EMB, p_w2h, p_w2l, HID, EMB, K2PAD);
        }

        // GEMM1: tmp = relu(aggr @ W1 + b1) -> split bf16 [*, 640]
        {
            dim3 grid(W1T_ROWS / 128, Mtiles);
            k_mma_gemm<<<grid, 256, MMA_SMEM>>>(p_ah, p_al, p_w1h, p_w1l,
                                                b1 + l * HID,
                                                N_NODES_C, HID, K1PAD,
                                                nullptr, 0, p_th, p_tl, K2PAD, 0, 1);
        }
        // GEMM2: h = tmp @ W2 + b2 (+relu) -> fp32 [*, 300]
        {
            dim3 grid(W2T_ROWS / 128, Mtiles);
            k_mma_gemm<<<grid, 256, MMA_SMEM>>>(p_th, p_tl, p_w2h, p_w2l,
                                                b2 + l * EMB,
                                                N_NODES_C, EMB, K2PAD,
                                                p_h, EMB, nullptr, nullptr, 0, 1,
                                                (l < NLAYER - 1) ? 1 : 0);
        }
    }

    // 4. global mean pool (segment reduction; batch sorted)
    k_pool_seg<<<N_GRAPHS_C, 96>>>();

    // 5. feat_lin + pred head
    {
        dim3 grid((FEAT + GBN - 1) / GBN, (N_GRAPHS_C + GBM - 1) / GBM);
        k_gemm128<<<grid, 256>>>(p_hg, feat_W, feat_b, out_hg,
                                 N_GRAPHS_C, FEAT, EMB, 0);
    }
    {
        dim3 grid((FEAT / 2 + GBN - 1) / GBN, (N_GRAPHS_C + GBM - 1) / GBM);
        k_gemm128<<<grid, 256>>>(out_hg, p0_W, p0_b, p_p,
                                 N_GRAPHS_C, FEAT / 2, FEAT, 1);
        k_gemm128<<<grid, 256>>>(p_p, p1_W, p1_b, p_pb,
                                 N_GRAPHS_C, FEAT / 2, FEAT / 2, 1);
    }
    {
        dim3 grid((OUTD + GBN - 1) / GBN, (N_GRAPHS_C + GBM - 1) / GBM);
        k_gemm128<<<grid, 256>>>(p_pb, p2_W, p2_b, out_proj,
                                 N_GRAPHS_C, OUTD, FEAT / 2, 0);
    }
}